// round 2
// baseline (speedup 1.0000x reference)
#include <cuda_runtime.h>

#define NA   100000
#define NP_  300000
#define NE   1000000
#define CIN  128
#define H    64

// ---------------- scratch (device globals; no allocation allowed) ------------
__device__ __align__(16) float g_a0  [NA  * H];   // projected author feats
__device__ __align__(16) float g_aggP[NP_ * H];   // paper-side aggregation
__device__ __align__(16) float g_aggA[NA  * H];   // author-side aggregation
__device__ __align__(16) float g_p1  [NP_ * H];
__device__ __align__(16) float g_p2  [NP_ * H];
__device__ __align__(16) float g_a1  [NA  * H];
__device__ __align__(16) float g_rcpP[NP_];       // counts, then reciprocals
__device__ __align__(16) float g_rcpA[NA];

// ---------------- zero kernels ----------------------------------------------
__global__ __launch_bounds__(256) void k_zero_all() {
    int i0 = blockIdx.x * blockDim.x + threadIdx.x;
    int stride = gridDim.x * blockDim.x;
    float4 z = make_float4(0.f, 0.f, 0.f, 0.f);
    float4* A = (float4*)g_aggP;
    for (int i = i0; i < NP_ * H / 4; i += stride) A[i] = z;
    float4* B = (float4*)g_aggA;
    for (int i = i0; i < NA * H / 4; i += stride) B[i] = z;
    for (int i = i0; i < NP_; i += stride) g_rcpP[i] = 0.f;
    for (int i = i0; i < NA;  i += stride) g_rcpA[i] = 0.f;
}

__global__ __launch_bounds__(256) void k_zero_aggP() {
    int i0 = blockIdx.x * blockDim.x + threadIdx.x;
    int stride = gridDim.x * blockDim.x;
    float4 z = make_float4(0.f, 0.f, 0.f, 0.f);
    float4* A = (float4*)g_aggP;
    for (int i = i0; i < NP_ * H / 4; i += stride) A[i] = z;
}

// ---------------- degrees + reciprocal --------------------------------------
__global__ __launch_bounds__(256) void k_deg(const int* __restrict__ src,
                                             const int* __restrict__ dst) {
    int i0 = blockIdx.x * blockDim.x + threadIdx.x;
    int stride = gridDim.x * blockDim.x;
    for (int e = i0; e < NE; e += stride) {
        atomicAdd(&g_rcpP[dst[e]], 1.f);
        atomicAdd(&g_rcpA[src[e]], 1.f);
    }
}

__global__ __launch_bounds__(256) void k_rcp() {
    int i0 = blockIdx.x * blockDim.x + threadIdx.x;
    int stride = gridDim.x * blockDim.x;
    for (int i = i0; i < NP_; i += stride) g_rcpP[i] = 1.f / fmaxf(g_rcpP[i], 1.f);
    for (int i = i0; i < NA;  i += stride) g_rcpA[i] = 1.f / fmaxf(g_rcpA[i], 1.f);
}

// ---------------- a0 = AF @ Wproj + bproj  ([NA,128]@[128,64]) ---------------
// 16 rows per block, 256 threads: thread = (col j, row-group rg of 4 rows).
__global__ __launch_bounds__(256) void k_proj(const float* __restrict__ A,
                                              const float* __restrict__ W,
                                              const float* __restrict__ b) {
    __shared__ __align__(16) float sW[CIN * H];     // 32 KB
    __shared__ __align__(16) float sX[CIN][20];     // transposed x tile, pad 20
    int t = threadIdx.x;
    int row0 = blockIdx.x * 16;

    const float4* W4 = (const float4*)W;
    float4* sW4 = (float4*)sW;
    #pragma unroll 4
    for (int i = t; i < CIN * H / 4; i += 256) sW4[i] = W4[i];

    for (int i = t; i < 16 * CIN; i += 256) {
        int r = i >> 7, k = i & 127;
        sX[k][r] = A[(row0 + r) * CIN + k];
    }
    __syncthreads();

    int j = t & 63, rg = t >> 6;
    float bj = b[j];
    float a0 = bj, a1 = bj, a2 = bj, a3 = bj;
    #pragma unroll 8
    for (int k = 0; k < CIN; k++) {
        float w = sW[k * H + j];
        float4 x = *(const float4*)&sX[k][rg * 4];
        a0 += x.x * w; a1 += x.y * w; a2 += x.z * w; a3 += x.w * w;
    }
    int r0 = row0 + rg * 4;
    g_a0[(r0 + 0) * H + j] = a0;
    g_a0[(r0 + 1) * H + j] = a1;
    g_a0[(r0 + 2) * H + j] = a2;
    g_a0[(r0 + 3) * H + j] = a3;
}

// ---------------- vector reduction helper ------------------------------------
__device__ __forceinline__ void red_add_v4(float* p, float4 v) {
    asm volatile("red.global.add.v4.f32 [%0], {%1,%2,%3,%4};"
                 :: "l"(p), "f"(v.x), "f"(v.y), "f"(v.z), "f"(v.w) : "memory");
}

// ---------------- scatter pass 1: aggP += a0[src], aggA += p0[dst] -----------
// 16 work items per edge (one float4 each); consecutive threads = same edge.
__global__ __launch_bounds__(256) void k_scatter1(const int* __restrict__ src,
                                                  const int* __restrict__ dst,
                                                  const float* __restrict__ p0) {
    long total = (long)NE * 16;
    long stride = (long)gridDim.x * blockDim.x;
    for (long i = (long)blockIdx.x * blockDim.x + threadIdx.x; i < total; i += stride) {
        int e = (int)(i >> 4), q = (int)(i & 15);
        int s = src[e], d = dst[e];
        float4 va = *(const float4*)&g_a0[s * H + q * 4];
        float4 vp = *(const float4*)&p0[d * H + q * 4];
        red_add_v4(&g_aggP[d * H + q * 4], va);
        red_add_v4(&g_aggA[s * H + q * 4], vp);
    }
}

// ---------------- scatter pass 2: aggP += a1[src] ----------------------------
__global__ __launch_bounds__(256) void k_scatter2(const int* __restrict__ src,
                                                  const int* __restrict__ dst) {
    long total = (long)NE * 16;
    long stride = (long)gridDim.x * blockDim.x;
    for (long i = (long)blockIdx.x * blockDim.x + threadIdx.x; i < total; i += stride) {
        int e = (int)(i >> 4), q = (int)(i & 15);
        int s = src[e], d = dst[e];
        float4 va = *(const float4*)&g_a1[s * H + q * 4];
        red_add_v4(&g_aggP[d * H + q * 4], va);
    }
}

// ---------------- SAGE layer: out = relu((agg*rcp) @ Wl + bl + xd @ Wr) ------
// mode 0: paper conv1 (xd = p0 input ptr)   -> g_p1
// mode 1: author conv1 (xd = g_a0)          -> g_a1
// mode 2: paper conv2 (xd = g_p1)           -> g_p2
__global__ __launch_bounds__(256) void k_conv(const float* __restrict__ xd_in,
                                              const float* __restrict__ Wl,
                                              const float* __restrict__ bl,
                                              const float* __restrict__ Wr,
                                              int mode) {
    const float* agg; const float* rcp; const float* xd; float* out;
    if (mode == 0)      { agg = g_aggP; rcp = g_rcpP; xd = xd_in; out = g_p1; }
    else if (mode == 1) { agg = g_aggA; rcp = g_rcpA; xd = g_a0;  out = g_a1; }
    else                { agg = g_aggP; rcp = g_rcpP; xd = g_p1;  out = g_p2; }

    __shared__ __align__(16) float sWl[H * H];      // 16 KB
    __shared__ __align__(16) float sWr[H * H];      // 16 KB
    __shared__ __align__(16) float sXa[H][20];      // 5 KB transposed agg tile
    __shared__ __align__(16) float sXd[H][20];      // 5 KB transposed dst tile

    int t = threadIdx.x;
    int row0 = blockIdx.x * 16;

    #pragma unroll 4
    for (int i = t; i < H * H / 4; i += 256) {
        ((float4*)sWl)[i] = ((const float4*)Wl)[i];
        ((float4*)sWr)[i] = ((const float4*)Wr)[i];
    }
    for (int i = t; i < 16 * H; i += 256) {
        int r = i >> 6, k = i & 63;
        int row = row0 + r;
        sXa[k][r] = agg[row * H + k] * rcp[row];
        sXd[k][r] = xd[row * H + k];
    }
    __syncthreads();

    int j = t & 63, rg = t >> 6;
    float b = bl[j];
    float a0 = b, a1 = b, a2 = b, a3 = b;
    #pragma unroll 8
    for (int k = 0; k < H; k++) {
        float wl = sWl[k * H + j];
        float wr = sWr[k * H + j];
        float4 xa = *(const float4*)&sXa[k][rg * 4];
        float4 xv = *(const float4*)&sXd[k][rg * 4];
        a0 += xa.x * wl + xv.x * wr;
        a1 += xa.y * wl + xv.y * wr;
        a2 += xa.z * wl + xv.z * wr;
        a3 += xa.w * wl + xv.w * wr;
    }
    int r0 = row0 + rg * 4;
    out[(r0 + 0) * H + j] = fmaxf(a0, 0.f);
    out[(r0 + 1) * H + j] = fmaxf(a1, 0.f);
    out[(r0 + 2) * H + j] = fmaxf(a2, 0.f);
    out[(r0 + 3) * H + j] = fmaxf(a3, 0.f);
}

// ---------------- MLP head: out = relu(p2@W1+b1) @ W2 + b2 -------------------
__global__ __launch_bounds__(256) void k_mlp(const float* __restrict__ W1,
                                             const float* __restrict__ b1,
                                             const float* __restrict__ W2,
                                             const float* __restrict__ b2,
                                             float* __restrict__ out) {
    __shared__ __align__(16) float sW[H * H];
    __shared__ __align__(16) float sX[H][20];
    __shared__ float sRed[16][2];
    int t = threadIdx.x;
    int row0 = blockIdx.x * 16;

    #pragma unroll 4
    for (int i = t; i < H * H / 4; i += 256)
        ((float4*)sW)[i] = ((const float4*)W1)[i];
    for (int i = t; i < 16 * H; i += 256) {
        int r = i >> 6, k = i & 63;
        sX[k][r] = g_p2[(row0 + r) * H + k];
    }
    __syncthreads();

    int j = t & 63, rg = t >> 6;
    float b = b1[j];
    float w2j = W2[j];
    float a0 = b, a1 = b, a2 = b, a3 = b;
    #pragma unroll 8
    for (int k = 0; k < H; k++) {
        float w = sW[k * H + j];
        float4 x = *(const float4*)&sX[k][rg * 4];
        a0 += x.x * w; a1 += x.y * w; a2 += x.z * w; a3 += x.w * w;
    }
    float p[4];
    p[0] = fmaxf(a0, 0.f) * w2j;
    p[1] = fmaxf(a1, 0.f) * w2j;
    p[2] = fmaxf(a2, 0.f) * w2j;
    p[3] = fmaxf(a3, 0.f) * w2j;

    #pragma unroll
    for (int off = 16; off > 0; off >>= 1) {
        p[0] += __shfl_down_sync(0xffffffffu, p[0], off);
        p[1] += __shfl_down_sync(0xffffffffu, p[1], off);
        p[2] += __shfl_down_sync(0xffffffffu, p[2], off);
        p[3] += __shfl_down_sync(0xffffffffu, p[3], off);
    }
    int lane = t & 31, w = t >> 5;
    if (lane == 0) {
        #pragma unroll
        for (int i = 0; i < 4; i++) sRed[rg * 4 + i][w & 1] = p[i];
    }
    __syncthreads();
    if (t < 16) out[row0 + t] = sRed[t][0] + sRed[t][1] + b2[0];
}

// ---------------- host driver -----------------------------------------------
extern "C" void kernel_launch(void* const* d_in, const int* in_sizes, int n_in,
                              void* d_out, int out_size) {
    const float* AF     = (const float*)d_in[0];
    const float* P0     = (const float*)d_in[1];
    const float* Wproj  = (const float*)d_in[2];
    const float* bproj  = (const float*)d_in[3];
    const float* c1p_Wl = (const float*)d_in[4];
    const float* c1p_bl = (const float*)d_in[5];
    const float* c1p_Wr = (const float*)d_in[6];
    const float* c1a_Wl = (const float*)d_in[7];
    const float* c1a_bl = (const float*)d_in[8];
    const float* c1a_Wr = (const float*)d_in[9];
    const float* c2p_Wl = (const float*)d_in[10];
    const float* c2p_bl = (const float*)d_in[11];
    const float* c2p_Wr = (const float*)d_in[12];
    // c2a_* (d_in[13..15]) are dead code in the reference
    const float* W1     = (const float*)d_in[16];
    const float* b1     = (const float*)d_in[17];
    const float* W2     = (const float*)d_in[18];
    const float* b2     = (const float*)d_in[19];
    const int*   src    = (const int*)d_in[20];
    const int*   dst    = (const int*)d_in[21];
    float* out = (float*)d_out;

    k_zero_all<<<2048, 256>>>();
    k_deg<<<1024, 256>>>(src, dst);
    k_rcp<<<(NP_ + 255) / 256, 256>>>();
    k_proj<<<NA / 16, 256>>>(AF, Wproj, bproj);
    k_scatter1<<<8192, 256>>>(src, dst, P0);
    k_conv<<<NP_ / 16, 256>>>(P0, c1p_Wl, c1p_bl, c1p_Wr, 0);
    k_conv<<<NA / 16, 256>>>(nullptr, c1a_Wl, c1a_bl, c1a_Wr, 1);
    k_zero_aggP<<<2048, 256>>>();
    k_scatter2<<<8192, 256>>>(src, dst);
    k_conv<<<NP_ / 16, 256>>>(nullptr, c2p_Wl, c2p_bl, c2p_Wr, 2);
    k_mlp<<<NP_ / 16, 256>>>(W1, b1, W2, b2, out);
}

// round 4
// speedup vs baseline: 1.0575x; 1.0575x over previous
#include <cuda_runtime.h>

#define NA   100000
#define NP_  300000
#define NE   1000000
#define H    64
#define KC   32                 // k-chunk per smem stage

// ---------------- scratch (device globals; no allocation allowed) ------------
__device__ __align__(16) float g_a0  [NA  * H];
__device__ __align__(16) float g_aggP[NP_ * H];   // also reused as h (mlp1 out)
__device__ __align__(16) float g_aggA[NA  * H];
__device__ __align__(16) float g_p1  [NP_ * H];
__device__ __align__(16) float g_p2  [NP_ * H];
__device__ __align__(16) float g_a1  [NA  * H];
__device__ __align__(16) float g_rcpP[NP_];
__device__ __align__(16) float g_rcpA[NA];

// ---------------- f32x2 helpers ----------------------------------------------
union F4U2 { float4 f4; ulonglong2 u2; };

__device__ __forceinline__ unsigned long long fma2(unsigned long long a,
                                                   unsigned long long b,
                                                   unsigned long long c) {
    unsigned long long d;
    asm("fma.rn.f32x2 %0, %1, %2, %3;" : "=l"(d) : "l"(a), "l"(b), "l"(c));
    return d;
}
__device__ __forceinline__ unsigned long long splat2(float v) {
    unsigned long long s;
    asm("mov.b64 %0, {%1, %1};" : "=l"(s) : "f"(v));
    return s;
}

// ---------------- zero kernels ----------------------------------------------
__global__ __launch_bounds__(256) void k_zero_all() {
    int i0 = blockIdx.x * blockDim.x + threadIdx.x;
    int stride = gridDim.x * blockDim.x;
    float4 z = make_float4(0.f, 0.f, 0.f, 0.f);
    float4* A = (float4*)g_aggP;
    for (int i = i0; i < NP_ * H / 4; i += stride) A[i] = z;
    float4* B = (float4*)g_aggA;
    for (int i = i0; i < NA * H / 4; i += stride) B[i] = z;
    for (int i = i0; i < NP_; i += stride) g_rcpP[i] = 0.f;
    for (int i = i0; i < NA;  i += stride) g_rcpA[i] = 0.f;
}

__global__ __launch_bounds__(256) void k_zero_aggP() {
    int i0 = blockIdx.x * blockDim.x + threadIdx.x;
    int stride = gridDim.x * blockDim.x;
    float4 z = make_float4(0.f, 0.f, 0.f, 0.f);
    float4* A = (float4*)g_aggP;
    for (int i = i0; i < NP_ * H / 4; i += stride) A[i] = z;
}

// ---------------- degrees + reciprocal --------------------------------------
__global__ __launch_bounds__(256) void k_deg(const int* __restrict__ src,
                                             const int* __restrict__ dst) {
    int i0 = blockIdx.x * blockDim.x + threadIdx.x;
    int stride = gridDim.x * blockDim.x;
    for (int e = i0; e < NE; e += stride) {
        atomicAdd(&g_rcpP[dst[e]], 1.f);
        atomicAdd(&g_rcpA[src[e]], 1.f);
    }
}

__global__ __launch_bounds__(256) void k_rcp() {
    int i0 = blockIdx.x * blockDim.x + threadIdx.x;
    int stride = gridDim.x * blockDim.x;
    for (int i = i0; i < NP_; i += stride) g_rcpP[i] = 1.f / fmaxf(g_rcpP[i], 1.f);
    for (int i = i0; i < NA;  i += stride) g_rcpA[i] = 1.f / fmaxf(g_rcpA[i], 1.f);
}

// ---------------- generic GEMM: out = op( (x .* scale?) @ W + bias? ) --------
// N rows, K in {64,128}. 64 rows x 64 cols per block; thread = 2 rows x 8 cols.
// x tile stored pre-splatted as f32x2 {v,v}; W pairs natural from LDS.128.
// flags: 1 = add existing out, 2 = relu.
__global__ __launch_bounds__(256) void k_gemm(
    const float* __restrict__ x, const float* __restrict__ W,
    const float* __restrict__ bias, const float* __restrict__ scale,
    float* __restrict__ out, int N, int K, int flags)
{
    __shared__ __align__(16) unsigned long long sXd[KC][66];  // [k][row] splatted
    __shared__ __align__(16) float sW[KC][64];                // [k][col]

    int t = threadIdx.x;
    int row0 = blockIdx.x * 64;
    int tj  = t & 7;            // 8 col groups
    int tr  = t >> 3;           // 32 row-pair groups
    int r2  = tr * 2;
    int j4a = tj * 4;
    int j4b = j4a + 32;

    // acc[row 0/1][half a/b][colpair 0/1]
    unsigned long long acc[2][2][2];
    if (bias) {
        F4U2 ba, bb;
        ba.f4 = *(const float4*)&bias[j4a];
        bb.f4 = *(const float4*)&bias[j4b];
        acc[0][0][0] = ba.u2.x; acc[0][0][1] = ba.u2.y;
        acc[0][1][0] = bb.u2.x; acc[0][1][1] = bb.u2.y;
        acc[1][0][0] = ba.u2.x; acc[1][0][1] = ba.u2.y;
        acc[1][1][0] = bb.u2.x; acc[1][1][1] = bb.u2.y;
    } else {
        #pragma unroll
        for (int a = 0; a < 2; a++)
            #pragma unroll
            for (int b = 0; b < 2; b++)
                #pragma unroll
                for (int c = 0; c < 2; c++) acc[a][b][c] = 0ull;
    }

    for (int k0 = 0; k0 < K; k0 += KC) {
        __syncthreads();
        // stage W chunk: KC*64 floats = 512 float4, 2 per thread
        #pragma unroll
        for (int i = 0; i < 2; i++) {
            int q = t + i * 256;
            int kk = q >> 4, j4 = (q & 15) * 4;
            *(float4*)&sW[kk][j4] = *(const float4*)&W[(k0 + kk) * H + j4];
        }
        // stage x chunk: KC*64 elems, 8 per thread, splat into f32x2
        #pragma unroll
        for (int i = 0; i < 8; i++) {
            int idx = t + i * 256;
            int k = idx & (KC - 1), r = idx >> 5;
            int rr = min(row0 + r, N - 1);
            float v = x[rr * K + k0 + k];
            if (scale) v *= scale[rr];
            sXd[k][r] = splat2(v);
        }
        __syncthreads();

        #pragma unroll
        for (int k = 0; k < KC; k++) {
            ulonglong2 xs = *(const ulonglong2*)&sXd[k][r2];  // rows r2, r2+1
            F4U2 wa, wb;
            wa.f4 = *(const float4*)&sW[k][j4a];
            wb.f4 = *(const float4*)&sW[k][j4b];
            acc[0][0][0] = fma2(xs.x, wa.u2.x, acc[0][0][0]);
            acc[0][0][1] = fma2(xs.x, wa.u2.y, acc[0][0][1]);
            acc[0][1][0] = fma2(xs.x, wb.u2.x, acc[0][1][0]);
            acc[0][1][1] = fma2(xs.x, wb.u2.y, acc[0][1][1]);
            acc[1][0][0] = fma2(xs.y, wa.u2.x, acc[1][0][0]);
            acc[1][0][1] = fma2(xs.y, wa.u2.y, acc[1][0][1]);
            acc[1][1][0] = fma2(xs.y, wb.u2.x, acc[1][1][0]);
            acc[1][1][1] = fma2(xs.y, wb.u2.y, acc[1][1][1]);
        }
    }

    #pragma unroll
    for (int r = 0; r < 2; r++) {
        int row = row0 + r2 + r;
        if (row >= N) continue;
        F4U2 oa, ob;
        oa.u2.x = acc[r][0][0]; oa.u2.y = acc[r][0][1];
        ob.u2.x = acc[r][1][0]; ob.u2.y = acc[r][1][1];
        float4 A = oa.f4, B = ob.f4;
        if (flags & 1) {
            float4 pa = *(const float4*)&out[row * H + j4a];
            float4 pb = *(const float4*)&out[row * H + j4b];
            A.x += pa.x; A.y += pa.y; A.z += pa.z; A.w += pa.w;
            B.x += pb.x; B.y += pb.y; B.z += pb.z; B.w += pb.w;
        }
        if (flags & 2) {
            A.x = fmaxf(A.x, 0.f); A.y = fmaxf(A.y, 0.f);
            A.z = fmaxf(A.z, 0.f); A.w = fmaxf(A.w, 0.f);
            B.x = fmaxf(B.x, 0.f); B.y = fmaxf(B.y, 0.f);
            B.z = fmaxf(B.z, 0.f); B.w = fmaxf(B.w, 0.f);
        }
        *(float4*)&out[row * H + j4a] = A;
        *(float4*)&out[row * H + j4b] = B;
    }
}

// ---------------- vector reduction helper ------------------------------------
__device__ __forceinline__ void red_add_v4(float* p, float4 v) {
    asm volatile("red.global.add.v4.f32 [%0], {%1,%2,%3,%4};"
                 :: "l"(p), "f"(v.x), "f"(v.y), "f"(v.z), "f"(v.w) : "memory");
}

// ---------------- scatter pass 1: aggP += a0[src], aggA += p0[dst] -----------
__global__ __launch_bounds__(256) void k_scatter1(const int* __restrict__ src,
                                                  const int* __restrict__ dst,
                                                  const float* __restrict__ p0) {
    long total = (long)NE * 16;
    long stride = (long)gridDim.x * blockDim.x;
    for (long i = (long)blockIdx.x * blockDim.x + threadIdx.x; i < total; i += stride) {
        int e = (int)(i >> 4), q = (int)(i & 15);
        int s = src[e], d = dst[e];
        float4 va = *(const float4*)&g_a0[s * H + q * 4];
        float4 vp = *(const float4*)&p0[d * H + q * 4];
        red_add_v4(&g_aggP[d * H + q * 4], va);
        red_add_v4(&g_aggA[s * H + q * 4], vp);
    }
}

// ---------------- scatter pass 2: aggP += a1[src] ----------------------------
__global__ __launch_bounds__(256) void k_scatter2(const int* __restrict__ src,
                                                  const int* __restrict__ dst) {
    long total = (long)NE * 16;
    long stride = (long)gridDim.x * blockDim.x;
    for (long i = (long)blockIdx.x * blockDim.x + threadIdx.x; i < total; i += stride) {
        int e = (int)(i >> 4), q = (int)(i & 15);
        int s = src[e], d = dst[e];
        float4 va = *(const float4*)&g_a1[s * H + q * 4];
        red_add_v4(&g_aggP[d * H + q * 4], va);
    }
}

// ---------------- final dot with W2: out[row] = h[row] . W2 + b2 -------------
__global__ __launch_bounds__(256) void k_mlp2(const float* __restrict__ h,
                                              const float* __restrict__ W2,
                                              const float* __restrict__ b2,
                                              float* __restrict__ out) {
    int gw = (blockIdx.x * blockDim.x + threadIdx.x) >> 5;   // one warp per row
    int lane = threadIdx.x & 31;
    if (gw >= NP_) return;
    float2 hv = *(const float2*)&h[gw * H + lane * 2];
    float2 wv = *(const float2*)&W2[lane * 2];
    float p = hv.x * wv.x + hv.y * wv.y;
    #pragma unroll
    for (int off = 16; off > 0; off >>= 1)
        p += __shfl_down_sync(0xffffffffu, p, off);
    if (lane == 0) out[gw] = p + b2[0];
}

// ---------------- host driver -----------------------------------------------
extern "C" void kernel_launch(void* const* d_in, const int* in_sizes, int n_in,
                              void* d_out, int out_size) {
    const float* AF     = (const float*)d_in[0];
    const float* P0     = (const float*)d_in[1];
    const float* Wproj  = (const float*)d_in[2];
    const float* bproj  = (const float*)d_in[3];
    const float* c1p_Wl = (const float*)d_in[4];
    const float* c1p_bl = (const float*)d_in[5];
    const float* c1p_Wr = (const float*)d_in[6];
    const float* c1a_Wl = (const float*)d_in[7];
    const float* c1a_bl = (const float*)d_in[8];
    const float* c1a_Wr = (const float*)d_in[9];
    const float* c2p_Wl = (const float*)d_in[10];
    const float* c2p_bl = (const float*)d_in[11];
    const float* c2p_Wr = (const float*)d_in[12];
    // c2a_* (d_in[13..15]) are dead code in the reference
    const float* W1     = (const float*)d_in[16];
    const float* b1     = (const float*)d_in[17];
    const float* W2     = (const float*)d_in[18];
    const float* b2     = (const float*)d_in[19];
    const int*   src    = (const int*)d_in[20];
    const int*   dst    = (const int*)d_in[21];
    float* out = (float*)d_out;

    float* a0   = nullptr; cudaGetSymbolAddress((void**)&a0,   g_a0);
    float* aggP = nullptr; cudaGetSymbolAddress((void**)&aggP, g_aggP);
    float* aggA = nullptr; cudaGetSymbolAddress((void**)&aggA, g_aggA);
    float* p1   = nullptr; cudaGetSymbolAddress((void**)&p1,   g_p1);
    float* p2   = nullptr; cudaGetSymbolAddress((void**)&p2,   g_p2);
    float* a1   = nullptr; cudaGetSymbolAddress((void**)&a1,   g_a1);
    float* rcpP = nullptr; cudaGetSymbolAddress((void**)&rcpP, g_rcpP);
    float* rcpA = nullptr; cudaGetSymbolAddress((void**)&rcpA, g_rcpA);

    const int GA = (NA  + 63) / 64;   // 1563
    const int GP = (NP_ + 63) / 64;   // 4688

    k_zero_all<<<2048, 256>>>();
    k_deg<<<1024, 256>>>(src, dst);
    k_rcp<<<(NP_ + 255) / 256, 256>>>();

    // a0 = AF @ Wproj + bproj
    k_gemm<<<GA, 256>>>(AF, Wproj, bproj, nullptr, a0, NA, 128, 0);

    k_scatter1<<<8192, 256>>>(src, dst, P0);

    // p1 = relu( (aggP*rcpP) @ c1p_Wl + c1p_bl + P0 @ c1p_Wr )
    k_gemm<<<GP, 256>>>(aggP, c1p_Wl, c1p_bl, rcpP, p1, NP_, 64, 0);
    k_gemm<<<GP, 256>>>(P0,   c1p_Wr, nullptr, nullptr, p1, NP_, 64, 3);

    // a1 = relu( (aggA*rcpA) @ c1a_Wl + c1a_bl + a0 @ c1a_Wr )
    k_gemm<<<GA, 256>>>(aggA, c1a_Wl, c1a_bl, rcpA, a1, NA, 64, 0);
    k_gemm<<<GA, 256>>>(a0,   c1a_Wr, nullptr, nullptr, a1, NA, 64, 3);

    k_zero_aggP<<<2048, 256>>>();
    k_scatter2<<<8192, 256>>>(src, dst);

    // p2 = relu( (aggP*rcpP) @ c2p_Wl + c2p_bl + p1 @ c2p_Wr )
    k_gemm<<<GP, 256>>>(aggP, c2p_Wl, c2p_bl, rcpP, p2, NP_, 64, 0);
    k_gemm<<<GP, 256>>>(p1,   c2p_Wr, nullptr, nullptr, p2, NP_, 64, 3);

    // h = relu(p2 @ W1 + b1)  (reuse aggP as h)
    k_gemm<<<GP, 256>>>(p2, W1, b1, nullptr, aggP, NP_, 64, 2);

    // out = h @ W2 + b2
    k_mlp2<<<(NP_ * 32 + 255) / 256, 256>>>(aggP, W2, b2, out);
}